// round 15
// baseline (speedup 1.0000x reference)
#include <cuda_runtime.h>
#include <cuda_bf16.h>
#include <cstdint>

// ---------------------------------------------------------------------------
// OrdinalPeakedCELoss — 4-stage deep pipeline, distance-3 prefetch (v6).
//  R11 (best, 37.4us) analysis: DRAM 58% because only ~92KB/SM of copy bytes
//  in flight (5 blocks x 1 outstanding 18.4KB) — critically balanced with
//  copy time ~= compute time per tile. R12/R13 regressions: distance-1
//  prefetch / per-warp tiny copies. v6:
//   * TILE=256, NSTAGES=4, prefetch distance 3  -> up to 3 outstanding
//     9.2KB copies per block; 6 blocks/SM (smem 37KB) -> ~166KB/SM in flight
//   * labels: distance-3 register queue (no smem, keeps the 6th block)
//   * compute body identical to R11 (arithmetic masks, ex2/lg2/rcp, padded
//     guards for clamp-free neighbor reads)
//  Deterministic: fixed tile->block map, fixed order, last-block double sum.
// ---------------------------------------------------------------------------

#define KCLS 9
#define NTHREADS 256
#define TILE 256                          /* rows per tile, 1 row/thread */
#define NSTAGES 4
#define PAD 4
#define SLICE_F (TILE * KCLS)             /* 2304 floats */
#define LOG_BYTES (SLICE_F * 4)           /* 9216 */
#define NBLK 888                          /* 148 x 6 */

#define ALPHA_C       0.4f
#define W_FAR_C       7.0f
#define DELTA_FAR_C   0.15f
#define W_TAIL_C      9.0f
#define W_LPEAK_C     12.0f
#define PROB_MARGIN_C 0.35f
#define W_EMD_C       1.2f
#define LOG2E_C       1.4426950408889634f
#define LN2_LN9_C     0.31546487678572877f

#define AWF (ALPHA_C * W_FAR_C)
#define AWT (ALPHA_C * W_TAIL_C)
#define AWL (ALPHA_C * W_LPEAK_C)
#define AWE (ALPHA_C * W_EMD_C)

__device__ float        g_partials[NBLK];
__device__ unsigned int g_count = 0;

__device__ __forceinline__ float f_ex2(float x){ float r; asm("ex2.approx.ftz.f32 %0, %1;" : "=f"(r) : "f"(x)); return r; }
__device__ __forceinline__ float f_lg2(float x){ float r; asm("lg2.approx.ftz.f32 %0, %1;" : "=f"(r) : "f"(x)); return r; }
__device__ __forceinline__ float f_rcp(float x){ float r; asm("rcp.approx.ftz.f32 %0, %1;" : "=f"(r) : "f"(x)); return r; }

__device__ __forceinline__ uint32_t smem_u32(const void* p) {
    uint32_t a;
    asm("{ .reg .u64 t; cvta.to.shared.u64 t, %1; cvt.u32.u64 %0, t; }" : "=r"(a) : "l"(p));
    return a;
}

#define MBAR_INIT(bar, cnt) \
    asm volatile("mbarrier.init.shared.b64 [%0], %1;" :: "r"(bar), "r"(cnt) : "memory")
#define MBAR_EXPECT_TX(bar, bytes) \
    asm volatile("mbarrier.arrive.expect_tx.shared.b64 _, [%0], %1;" :: "r"(bar), "r"(bytes) : "memory")
#define MBAR_WAIT(bar, ph) do {                                                   \
    asm volatile("{\n\t.reg .pred P;\n"                                           \
        "W_%=:\n\t"                                                               \
        "mbarrier.try_wait.parity.acquire.cta.shared::cta.b64 P, [%0], %1, 0x989680;\n\t" \
        "@P bra D_%=;\n\t"                                                        \
        "bra W_%=;\n"                                                             \
        "D_%=:\n\t}"                                                              \
        :: "r"(bar), "r"(ph) : "memory");                                         \
} while (0)
#define BULK_CP(dst, src, bytes, bar) \
    asm volatile("cp.async.bulk.shared::cta.global.mbarrier::complete_tx::bytes [%0], [%1], %2, [%3];" \
        :: "r"(dst), "l"(src), "r"(bytes), "r"(bar) : "memory")

__device__ __forceinline__ float cw_of(int k) {
    const float cw[KCLS] = {
        3.0f/95.0f, 7.0f/95.0f, 10.0f/95.0f, 10.0f/95.0f, 10.0f/95.0f,
        10.0f/95.0f, 10.0f/95.0f, 10.0f/95.0f, 25.0f/95.0f };
    return cw[k];
}

__device__ __forceinline__ uint32_t sel4(uint32_t a, uint32_t b, uint32_t c,
                                         uint32_t d, int s) {
    return (s == 0) ? a : (s == 1) ? b : (s == 2) ? c : d;
}

// Hot path: lrow readable at [-1] and [9] (padded buffer; OOR values finite,
// masked to zero).
__device__ __forceinline__ float row_loss(const float* __restrict__ lrow, int y,
                                          const float* __restrict__ s_ccw) {
    const float fy  = (float)y;
    const float fy1 = fy + 1.0f;

    float E = 0.0f, Q = 0.0f, A = 0.0f, tail = 0.0f, ef = 0.0f;

#pragma unroll
    for (int k = 0; k < KCLS; ++k) {
        float e = f_ex2(lrow[k] * LOG2E_C);            // exp(l_k)
        E += e;                                         // prefix; E_8 == S
        float u = cw_of(k) * E;                         // FMUL imm
        Q = fmaf(u, E, Q);                              // sum cw_k E_k^2
        float le = __saturatef(fy1 - (float)k);         // 1 iff k<=y
        A = fmaf(le, u, A);
        float s = fabsf((float)k - fy) - 1.0f;          // |d|-1
        float c = fmaxf(s, 0.0f);
        float h = e * c;
        ef = fmaxf(ef, fminf(h, e));                    // e*min(c,1)
        tail = fmaf(h, c * c, tail);                    // e*(|d|-1)^3
    }

    float invS = f_rcp(E);
    float ty = lrow[y] * LOG2E_C;
    float ey = f_ex2(ty);
    float el = f_ex2(lrow[y - 1] * LOG2E_C) * __saturatef(fy);         // 0 at y=0
    float er = f_ex2(lrow[y + 1] * LOG2E_C) * __saturatef(8.0f - fy);  // 0 at y=8
    float en = fmaxf(el, er);

    float farm  = fmaxf(fmaf(ef - ey, invS, DELTA_FAR_C),   0.0f);
    float lpeak = fmaxf(fmaf(en - ey, invS, PROB_MARGIN_C), 0.0f);
    float emd   = fmaf(Q, invS * invS, fmaf(-2.0f * A, invS, s_ccw[y]));

    float r = (f_lg2(E) - ty) * LN2_LN9_C;              // nll / ln 9
    r = fmaf(AWF, farm, r);
    r = fmaf(AWT, tail * invS, r);
    r = fmaf(AWL, lpeak, r);
    r = fmaf(AWE, emd, r);
    return r;
}

// Residue path (rare): clamped indices, direct global reads.
__device__ __noinline__ float row_loss_global(const float* __restrict__ g, int y,
                                              const float* __restrict__ s_ccw) {
    const float fy = (float)y;
    float E = 0.0f, Q = 0.0f, A = 0.0f, tail = 0.0f, ef = 0.0f;
    float lv[KCLS];
#pragma unroll
    for (int k = 0; k < KCLS; ++k) lv[k] = __ldg(&g[k]);
#pragma unroll
    for (int k = 0; k < KCLS; ++k) {
        float e = f_ex2(lv[k] * LOG2E_C);
        E += e;
        float u = cw_of(k) * E;
        Q = fmaf(u, E, Q);
        float le = __saturatef(fy + 1.0f - (float)k);
        A = fmaf(le, u, A);
        float s = fabsf((float)k - fy) - 1.0f;
        float c = fmaxf(s, 0.0f);
        float h = e * c;
        ef = fmaxf(ef, fminf(h, e));
        tail = fmaf(h, c * c, tail);
    }
    float invS = f_rcp(E);
    int yl = (y > 0) ? y - 1 : 0;
    int yr = (y < KCLS - 1) ? y + 1 : KCLS - 1;
    float ty = lv[y] * LOG2E_C;
    float ey = f_ex2(ty);
    float el = f_ex2(lv[yl] * LOG2E_C) * __saturatef(fy);
    float er = f_ex2(lv[yr] * LOG2E_C) * __saturatef(8.0f - fy);
    float en = fmaxf(el, er);
    float farm  = fmaxf(fmaf(ef - ey, invS, DELTA_FAR_C),   0.0f);
    float lpeak = fmaxf(fmaf(en - ey, invS, PROB_MARGIN_C), 0.0f);
    float emd   = fmaf(Q, invS * invS, fmaf(-2.0f * A, invS, s_ccw[y]));
    float r = (f_lg2(E) - ty) * LN2_LN9_C;
    r = fmaf(AWF, farm, r);
    r = fmaf(AWT, tail * invS, r);
    r = fmaf(AWL, lpeak, r);
    r = fmaf(AWE, emd, r);
    return r;
}

__global__ __launch_bounds__(NTHREADS, 6)
void opcel_pipe(const float* __restrict__ logits,
                const int*   __restrict__ y,
                float*       __restrict__ out,
                int B, int nblocks) {
    /* [PAD | stage0..stage3 contiguous | PAD] */
    __shared__ __align__(16) float s_log[2 * PAD + NSTAGES * SLICE_F];
    __shared__ __align__(8)  unsigned long long s_bar[NSTAGES];
    __shared__ float s_ccw[KCLS];
    __shared__ float s_red[NTHREADS / 32];
    __shared__ int   s_last;

    const int tid = threadIdx.x;
    const int bid = blockIdx.x;

    if (tid < KCLS) {
        const float ccw[KCLS] = {
            3.0f/95.0f, 10.0f/95.0f, 20.0f/95.0f, 30.0f/95.0f, 40.0f/95.0f,
            50.0f/95.0f, 60.0f/95.0f, 70.0f/95.0f, 1.0f };
        s_ccw[tid] = ccw[tid];
    }
    if (tid < PAD) {
        s_log[tid] = 0.0f;
        s_log[PAD + NSTAGES * SLICE_F + tid] = 0.0f;
    }
    if (tid < NSTAGES) MBAR_INIT(smem_u32(&s_bar[tid]), 1);
    __syncthreads();

    const uint32_t b0 = smem_u32(&s_bar[0]), b1 = smem_u32(&s_bar[1]);
    const uint32_t b2 = smem_u32(&s_bar[2]), b3 = smem_u32(&s_bar[3]);
    const uint32_t d0 = smem_u32(&s_log[PAD + 0 * SLICE_F]);
    const uint32_t d1 = smem_u32(&s_log[PAD + 1 * SLICE_F]);
    const uint32_t d2 = smem_u32(&s_log[PAD + 2 * SLICE_F]);
    const uint32_t d3 = smem_u32(&s_log[PAD + 3 * SLICE_F]);
    const float* lg_base = &s_log[PAD];

    const int ntiles = B / TILE;
    int my_n = 0;
    for (long long t = bid; t < ntiles; t += nblocks) ++my_n;

    // Prologue: issue copies for tiles 0..2 into stages 0..2; label queue.
    if (tid == 0) {
#pragma unroll
        for (int p = 0; p < 3; ++p) {
            if (p < my_n) {
                long long tp = (long long)bid + (long long)p * nblocks;
                uint32_t bar = sel4(b0, b1, b2, b3, p);
                uint32_t dst = sel4(d0, d1, d2, d3, p);
                MBAR_EXPECT_TX(bar, LOG_BYTES);
                BULK_CP(dst, (const void*)(logits + tp * SLICE_F), LOG_BYTES, bar);
            }
        }
    }
    int yq0 = 0, yq1 = 0, yq2 = 0;
    if (0 < my_n) yq0 = __ldg(&y[((long long)bid + 0LL * nblocks) * TILE + tid]);
    if (1 < my_n) yq1 = __ldg(&y[((long long)bid + 1LL * nblocks) * TILE + tid]);
    if (2 < my_n) yq2 = __ldg(&y[((long long)bid + 2LL * nblocks) * TILE + tid]);

    float acc = 0.0f;
    int s = 0, par = 0;

    for (int j = 0; j < my_n; ++j) {
        int yn = 0;
        if ((j + 3) < my_n) {
            long long tn = (long long)bid + (long long)(j + 3) * nblocks;
            if (tid == 0) {
                int ps = s + 3; if (ps >= NSTAGES) ps -= NSTAGES;   /* == (j+3)%4 */
                uint32_t bar = sel4(b0, b1, b2, b3, ps);
                uint32_t dst = sel4(d0, d1, d2, d3, ps);
                MBAR_EXPECT_TX(bar, LOG_BYTES);
                BULK_CP(dst, (const void*)(logits + tn * SLICE_F), LOG_BYTES, bar);
            }
            yn = __ldg(&y[tn * TILE + tid]);     /* consumed 3 tiles later */
        }

        MBAR_WAIT(sel4(b0, b1, b2, b3, s), par);

        acc += row_loss(lg_base + s * SLICE_F + tid * KCLS, yq0, s_ccw);
        __syncthreads();                         /* stage s free for reuse */

        yq0 = yq1; yq1 = yq2; yq2 = yn;
        if (++s == NSTAGES) { s = 0; par ^= 1; }
    }

    // Residue rows (B % TILE) -> block 0, direct global reads.
    if (bid == 0) {
        for (int r = ntiles * TILE + tid; r < B; r += NTHREADS)
            acc += row_loss_global(logits + (long long)r * KCLS, __ldg(&y[r]), s_ccw);
    }

    // Block reduction
#pragma unroll
    for (int off = 16; off > 0; off >>= 1)
        acc += __shfl_down_sync(0xFFFFFFFFu, acc, off);
    int lane = tid & 31, wid = tid >> 5;
    if (lane == 0) s_red[wid] = acc;
    __syncthreads();
    if (tid == 0) {
        float v = 0.0f;
#pragma unroll
        for (int w = 0; w < NTHREADS / 32; ++w) v += s_red[w];
        g_partials[bid] = v;
        __threadfence();
        unsigned int t = atomicAdd(&g_count, 1u);
        s_last = (t == (unsigned int)(nblocks - 1));
    }
    __syncthreads();

    // Last block: deterministic final reduction in double
    if (s_last) {
        double d = 0.0;
        for (int i = tid; i < nblocks; i += NTHREADS)
            d += (double)g_partials[i];
#pragma unroll
        for (int off = 16; off > 0; off >>= 1)
            d += __shfl_down_sync(0xFFFFFFFFu, d, off);

        __shared__ double s_d[NTHREADS / 32];
        if (lane == 0) s_d[wid] = d;
        __syncthreads();
        if (tid == 0) {
            double tot = 0.0;
#pragma unroll
            for (int w = 0; w < NTHREADS / 32; ++w) tot += s_d[w];
            out[0] = (float)(tot / (double)B);
            g_count = 0;   /* self-reset for graph replay */
        }
    }
}

extern "C" void kernel_launch(void* const* d_in, const int* in_sizes, int n_in,
                              void* d_out, int out_size) {
    const float* logits = (const float*)d_in[0];
    const int*   y      = (const int*)d_in[1];
    float* out = (float*)d_out;
    int B = in_sizes[1];

    int ntiles = B / TILE;
    int nblocks = NBLK;
    if (nblocks > ntiles && ntiles > 0) nblocks = ntiles;
    if (nblocks < 1) nblocks = 1;

    opcel_pipe<<<nblocks, NTHREADS>>>(logits, y, out, B, nblocks);
}